// round 9
// baseline (speedup 1.0000x reference)
#include <cuda_runtime.h>
#include <cuda_fp16.h>
#include <math.h>

#define GHH 224
#define GWW 224
#define PLANE (GHH*GWW)
#define TS 16
#define HALO 3
#define THALO (TS + 2*HALO)    // 22
#define NPIX (THALO*THALO)     // 484
#define CH 32
#define CHP_H 40               // padded half-channel stride in smem: 80B lane stride, conflict-free
#define NP 49

// Scratch (no allocations allowed).
__device__ float    g_f0[8*972];
__device__ float    g_bufA[8*3*PLANE];
__device__ float    g_bufB[8*3*PLANE];
// q keys, channel-pair-major planes: [stage][b][m=0..15][PLANE], each elem = half2 (ch 2m, 2m+1)
__device__ unsigned int g_q[4ull*8*16*PLANE];

__device__ __forceinline__ int refl(int i, int n) {
    if (i < 0) i = -i;
    if (i >= n) i = 2*n - 2 - i;
    return i;
}

// Abramowitz-Stegun 7.1.26, |abs err| <= 1.5e-7 (far below fp16-q rounding)
__device__ __forceinline__ float erf_fast(float x) {
    float ax = fabsf(x);
    float t = __frcp_rn(fmaf(0.3275911f, ax, 1.0f));
    float p = fmaf(1.061405429f, t, -1.453152027f);
    p = fmaf(p, t, 1.421413741f);
    p = fmaf(p, t, -0.284496736f);
    p = fmaf(p, t, 0.254829592f);
    p = p * t;
    float e = 1.0f - p * __expf(-ax*ax);
    return copysignf(e, x);
}

__device__ __forceinline__ float gelu_fast(float x) {
    return 0.5f * x * (1.0f + erf_fast(x * 0.7071067811865476f));
}

__device__ __forceinline__ __half2 h2cast(unsigned int u) {
    return *reinterpret_cast<__half2*>(&u);
}

// ---------------------------------------------------------------- linear ----
__global__ void linear_kernel(const float* __restrict__ x,
                              const float* __restrict__ w,
                              const float* __restrict__ bias)
{
    int gw = blockIdx.x * 4 + (threadIdx.x >> 5);
    int lane = threadIdx.x & 31;
    if (gw >= 8*972) return;
    int b = gw / 972, o = gw % 972;
    const float* xr = x + b*1000;
    const float* wr = w + o*1000;
    float s = 0.f;
    for (int k = lane; k < 1000; k += 32) s += xr[k] * wr[k];
    #pragma unroll
    for (int off = 16; off; off >>= 1) s += __shfl_xor_sync(0xffffffffu, s, off);
    if (lane == 0) g_f0[b*972 + o] = s + bias[o];
}

// ---------------------------------------------------------------- bicubic ----
__device__ __forceinline__ float cubicw(float d) {
    d = fabsf(d);
    const float a = -0.75f;
    if (d <= 1.f) return ((a + 2.f)*d - (a + 3.f))*d*d + 1.f;
    if (d <  2.f) return (((d - 5.f)*d + 8.f)*d - 4.f) * a;
    return 0.f;
}

__global__ void bicubic18_kernel()
{
    int idx = blockIdx.x * blockDim.x + threadIdx.x;
    if (idx >= 8*3*PLANE) return;
    int x  = idx % GWW;
    int y  = (idx / GWW) % GHH;
    int bc = idx / PLANE;
    float xs = (x + 0.5f) * (18.0f/224.0f) - 0.5f;
    float ys = (y + 0.5f) * (18.0f/224.0f) - 0.5f;
    int x0 = (int)floorf(xs), y0 = (int)floorf(ys);
    float tx = xs - (float)x0, ty = ys - (float)y0;
    float wx[4], wy[4]; int ix[4], iy[4];
    #pragma unroll
    for (int k = 0; k < 4; k++) {
        wx[k] = cubicw(tx - (float)(k-1)); ix[k] = min(max(x0 + k - 1, 0), 17);
        wy[k] = cubicw(ty - (float)(k-1)); iy[k] = min(max(y0 + k - 1, 0), 17);
    }
    const float* f = g_f0 + bc*324;
    float acc = 0.f;
    #pragma unroll
    for (int i = 0; i < 4; i++) {
        float r = 0.f;
        #pragma unroll
        for (int j = 0; j < 4; j++) r += wx[j] * f[iy[i]*18 + ix[j]];
        acc += wy[i] * r;
    }
    g_bufA[idx] = acc;
}

// --------------------------------------------------------------- q-proj ----
// 4 pixels per thread; all 4 stages; weights LDS amortized x4; coalesced
// plane-major half2 stores. Block = 256 threads covers 1024 consecutive pixels
// of one batch image (PLANE = 49*1024 exactly).
__global__ __launch_bounds__(256)
void qproj_kernel(const float* __restrict__ guidance,
                  const float* __restrict__ w1s, const float* __restrict__ b1s,
                  const float* __restrict__ w2s, const float* __restrict__ b2s)
{
    __shared__ float   s_w1[4*96];
    __shared__ float   s_b1[4*32];
    __shared__ float   s_b2[4*32];
    __shared__ __half2 s_w2[4*32*16];   // [stage][out j][in pair k]

    const int tid = threadIdx.x;
    for (int i = tid; i < 4*96; i += 256) s_w1[i] = w1s[i];
    for (int i = tid; i < 4*32; i += 256) { s_b1[i] = b1s[i]; s_b2[i] = b2s[i]; }
    for (int i = tid; i < 4*32*16; i += 256) {
        int k = i & 15; int sj = i >> 4;
        s_w2[i] = __floats2half2_rn(w2s[sj*32 + 2*k], w2s[sj*32 + 2*k + 1]);
    }
    __syncthreads();

    const int b    = blockIdx.x / 49;
    const int base = (blockIdx.x % 49) * 1024 + tid;   // gi for i=0 (stride 256)
    const float* gb = guidance + (size_t)b * 3 * PLANE;

    float g0[4], g1[4], g2[4];
    #pragma unroll
    for (int i = 0; i < 4; i++) {
        int gi = base + i*256;
        g0[i] = gb[gi]; g1[i] = gb[PLANE + gi]; g2[i] = gb[2*PLANE + gi];
    }

    #pragma unroll 1
    for (int s = 0; s < 4; s++) {
        const float* w1 = s_w1 + s*96;
        const float* b1 = s_b1 + s*32;
        const float* b2 = s_b2 + s*32;
        const __half2* w2 = s_w2 + s*32*16;

        __half2 h2[4][16];
        #pragma unroll
        for (int k = 0; k < 16; k++) {
            float wa0 = w1[(2*k)*3], wa1 = w1[(2*k)*3+1], wa2 = w1[(2*k)*3+2], ba = b1[2*k];
            float wb0 = w1[(2*k+1)*3], wb1 = w1[(2*k+1)*3+1], wb2 = w1[(2*k+1)*3+2], bb = b1[2*k+1];
            #pragma unroll
            for (int i = 0; i < 4; i++) {
                float va = fmaf(wa0, g0[i], fmaf(wa1, g1[i], fmaf(wa2, g2[i], ba)));
                float vb = fmaf(wb0, g0[i], fmaf(wb1, g1[i], fmaf(wb2, g2[i], bb)));
                h2[i][k] = __floats2half2_rn(gelu_fast(va), gelu_fast(vb));
            }
        }

        unsigned int* qplane = g_q + ((size_t)(s*8 + b) * 16) * PLANE;
        #pragma unroll 1
        for (int m = 0; m < 16; m++) {
            const __half2* wr0 = w2 + (2*m)*16;
            const __half2* wr1 = wr0 + 16;
            __half2 a0[4], a1[4];
            #pragma unroll
            for (int i = 0; i < 4; i++) { a0[i] = __float2half2_rn(0.f); a1[i] = a0[i]; }
            #pragma unroll
            for (int k = 0; k < 16; k++) {
                __half2 w0 = wr0[k], w1h = wr1[k];
                #pragma unroll
                for (int i = 0; i < 4; i++) {
                    a0[i] = __hfma2(h2[i][k], w0,  a0[i]);
                    a1[i] = __hfma2(h2[i][k], w1h, a1[i]);
                }
            }
            float c0 = b2[2*m], c1 = b2[2*m+1];
            #pragma unroll
            for (int i = 0; i < 4; i++) {
                float2 f0 = __half22float2(a0[i]);
                float2 f1 = __half22float2(a1[i]);
                __half2 qv = __floats2half2_rn(f0.x + f0.y + c0, f1.x + f1.y + c1);
                qplane[(size_t)m * PLANE + base + i*256] = *reinterpret_cast<unsigned int*>(&qv);
            }
        }
    }
}

// ------------------------------------------------------------- fused JBU ----
__global__ __launch_bounds__(256, 2)
void jbu_kernel(const float* __restrict__ temp_p, const float* __restrict__ sigma_p,
                int stage, int src_sel, int dst_sel, float* __restrict__ dst_ext)
{
    const float* hr_in = (src_sel == 0) ? g_bufA : g_bufB;
    float* out = (dst_sel == 2) ? dst_ext : ((dst_sel == 0) ? g_bufA : g_bufB);

    extern __shared__ float smem[];
    float* shr = smem;                      // [3][NPIX] = 1452
    float* ssp = shr + 3*NPIX;              // 49 -> 1501
    __half* sq = (__half*)(smem + 1504);    // 16B aligned

    const int tid = threadIdx.x;
    const int b   = blockIdx.z;
    const int ty0 = blockIdx.y * TS, tx0 = blockIdx.x * TS;

    if (tid < NP) {
        float sig = *sigma_p;
        int di = tid / 7, dj = tid % 7;
        float dy = -1.0f + (float)di * (1.0f/3.0f);
        float dx = -1.0f + (float)dj * (1.0f/3.0f);
        ssp[tid] = expf(-(dy*dy + dx*dx) / (2.0f*sig*sig));
    }

    const float* hb = hr_in + (size_t)b * 3 * PLANE;
    const unsigned int* qg = g_q + ((size_t)(stage*8 + b) * 16) * PLANE;

    // Halo fill: hr (fp32) + precomputed q (16 half2 planes per pixel).
    for (int i = tid; i < NPIX; i += 256) {
        int ly = i / THALO, lx = i % THALO;
        int gy = refl(ty0 + ly - HALO, GHH);
        int gx = refl(tx0 + lx - HALO, GWW);
        int gi = gy * GWW + gx;
        shr[i]        = hb[gi];
        shr[NPIX+i]   = hb[PLANE + gi];
        shr[2*NPIX+i] = hb[2*PLANE + gi];
        unsigned int* qd = (unsigned int*)(sq + i * CHP_H);
        #pragma unroll
        for (int m = 0; m < 16; m++) qd[m] = qg[(size_t)m * PLANE + gi];
    }
    __syncthreads();

    const int ty = tid / TS, tx = tid % TS;
    const int base = ty * THALO + tx;                  // top-left (di=0,dj=0) tap
    const __half* qb = sq + base * CHP_H;
    const __half* qc = sq + (base + HALO*THALO + HALO) * CHP_H;

    __half2 s2[NP];
    #pragma unroll
    for (int p = 0; p < NP; p++) s2[p] = __float2half2_rn(0.f);

    #pragma unroll 1
    for (int c4 = 0; c4 < 4; c4++) {           // 8 channels per iteration
        uint4 cu = ((const uint4*)qc)[c4];
        __half2 c0 = h2cast(cu.x), c1 = h2cast(cu.y), c2 = h2cast(cu.z), c3 = h2cast(cu.w);
        #pragma unroll
        for (int p = 0; p < NP; p++) {
            const int di = p / 7, dj = p % 7;
            uint4 tu = ((const uint4*)(qb + (di*THALO + dj)*CHP_H))[c4];
            __half2 acc = s2[p];
            acc = __hfma2(c0, h2cast(tu.x), acc);
            acc = __hfma2(c1, h2cast(tu.y), acc);
            acc = __hfma2(c2, h2cast(tu.z), acc);
            acc = __hfma2(c3, h2cast(tu.w), acc);
            s2[p] = acc;
        }
    }

    float tmp = expf(*temp_p);
    tmp = fminf(fmaxf(tmp, 1e-4f), 1e4f);

    float s[NP];
    float m = -1e30f;
    #pragma unroll
    for (int p = 0; p < NP; p++) {
        float2 f = __half22float2(s2[p]);
        s[p] = (f.x + f.y) * tmp;
        m = fmaxf(m, s[p]);
    }
    float sum = 0.f;
    #pragma unroll
    for (int p = 0; p < NP; p++) {
        float e = __expf(s[p] - m) * ssp[p];
        s[p] = e; sum += e;
    }
    float inv = 1.0f / fmaxf(sum, 1e-7f);

    float o0 = 0.f, o1 = 0.f, o2 = 0.f;
    #pragma unroll
    for (int p = 0; p < NP; p++) {
        const int di = p / 7, dj = p % 7;
        int ti = base + di*THALO + dj;
        o0 += s[p] * shr[ti];
        o1 += s[p] * shr[NPIX + ti];
        o2 += s[p] * shr[2*NPIX + ti];
    }
    int y = ty0 + ty, x = tx0 + tx;
    size_t ob = (size_t)b * 3 * PLANE + (size_t)y * GWW + x;
    out[ob]           = o0 * inv;
    out[ob +   PLANE] = o1 * inv;
    out[ob + 2*PLANE] = o2 * inv;
}

// ----------------------------------------------------------------- launch ----
extern "C" void kernel_launch(void* const* d_in, const int* in_sizes, int n_in,
                              void* d_out, int out_size)
{
    const float* x      = (const float*)d_in[0];
    const float* gd     = (const float*)d_in[1];
    const float* lw     = (const float*)d_in[2];
    const float* lb     = (const float*)d_in[3];
    const float* w1s    = (const float*)d_in[4];
    const float* b1s    = (const float*)d_in[5];
    const float* w2s    = (const float*)d_in[6];
    const float* b2s    = (const float*)d_in[7];
    const float* temps  = (const float*)d_in[8];
    const float* sigmas = (const float*)d_in[9];
    float* out = (float*)d_out;

    const int smem = 1504*4 + NPIX * CHP_H * 2;   // 6016 + 38720 = 44736 B
    static int smem_set = 0;
    if (!smem_set) {
        cudaFuncSetAttribute(jbu_kernel, cudaFuncAttributeMaxDynamicSharedMemorySize, smem);
        smem_set = 1;
    }

    linear_kernel<<<(8*972 + 3)/4, 128>>>(x, lw, lb);
    bicubic18_kernel<<<(8*3*PLANE + 255)/256, 256>>>();
    qproj_kernel<<<8*49, 256>>>(gd, w1s, b1s, w2s, b2s);

    dim3 grid(GWW/TS, GHH/TS, 8);
    jbu_kernel<<<grid, 256, smem>>>(temps + 0, sigmas + 0, 0, 0, 1, nullptr);
    jbu_kernel<<<grid, 256, smem>>>(temps + 1, sigmas + 1, 1, 1, 0, nullptr);
    jbu_kernel<<<grid, 256, smem>>>(temps + 2, sigmas + 2, 2, 0, 1, nullptr);
    jbu_kernel<<<grid, 256, smem>>>(temps + 3, sigmas + 3, 3, 1, 2, out);
}

// round 14
// speedup vs baseline: 1.0591x; 1.0591x over previous
#include <cuda_runtime.h>
#include <cuda_fp16.h>
#include <math.h>

#define GHH 224
#define GWW 224
#define PLANE (GHH*GWW)
#define TS 16
#define HALO 3
#define THALO (TS + 2*HALO)    // 22
#define NPIX (THALO*THALO)     // 484
#define CH 32
#define CHP_H 40               // padded half-channel stride in smem: 80B lane stride, conflict-free
#define NP 49

// Scratch (no allocations allowed).
__device__ float  g_f0[8*972];
__device__ float  g_bufA[8*3*PLANE];
__device__ float  g_bufB[8*3*PLANE];
// q keys, pixel-major: [stage][b][pixel][32ch] fp16 (64B per pixel, uint4-friendly)
__device__ __half g_q[4ull*8*PLANE*CH];

__device__ __forceinline__ int refl(int i, int n) {
    if (i < 0) i = -i;
    if (i >= n) i = 2*n - 2 - i;
    return i;
}

// Abramowitz-Stegun 7.1.26, |abs err| <= 1.5e-7 (validated on HW in Round 9, rel_err 5.79e-7)
__device__ __forceinline__ float erf_fast(float x) {
    float ax = fabsf(x);
    float t = __frcp_rn(fmaf(0.3275911f, ax, 1.0f));
    float p = fmaf(1.061405429f, t, -1.453152027f);
    p = fmaf(p, t, 1.421413741f);
    p = fmaf(p, t, -0.284496736f);
    p = fmaf(p, t, 0.254829592f);
    p = p * t;
    float e = 1.0f - p * __expf(-ax*ax);
    return copysignf(e, x);
}

__device__ __forceinline__ float gelu_fast(float x) {
    return 0.5f * x * (1.0f + erf_fast(x * 0.7071067811865476f));
}

__device__ __forceinline__ __half2 h2cast(unsigned int u) {
    return *reinterpret_cast<__half2*>(&u);
}

// ---------------------------------------------------------------- linear ----
__global__ void linear_kernel(const float* __restrict__ x,
                              const float* __restrict__ w,
                              const float* __restrict__ bias)
{
    int gw = blockIdx.x * 4 + (threadIdx.x >> 5);
    int lane = threadIdx.x & 31;
    if (gw >= 8*972) return;
    int b = gw / 972, o = gw % 972;
    const float* xr = x + b*1000;
    const float* wr = w + o*1000;
    float s = 0.f;
    for (int k = lane; k < 1000; k += 32) s += xr[k] * wr[k];
    #pragma unroll
    for (int off = 16; off; off >>= 1) s += __shfl_xor_sync(0xffffffffu, s, off);
    if (lane == 0) g_f0[b*972 + o] = s + bias[o];
}

// ---------------------------------------------------------------- bicubic ----
__device__ __forceinline__ float cubicw(float d) {
    d = fabsf(d);
    const float a = -0.75f;
    if (d <= 1.f) return ((a + 2.f)*d - (a + 3.f))*d*d + 1.f;
    if (d <  2.f) return (((d - 5.f)*d + 8.f)*d - 4.f) * a;
    return 0.f;
}

__global__ void bicubic18_kernel()
{
    int idx = blockIdx.x * blockDim.x + threadIdx.x;
    if (idx >= 8*3*PLANE) return;
    int x  = idx % GWW;
    int y  = (idx / GWW) % GHH;
    int bc = idx / PLANE;
    float xs = (x + 0.5f) * (18.0f/224.0f) - 0.5f;
    float ys = (y + 0.5f) * (18.0f/224.0f) - 0.5f;
    int x0 = (int)floorf(xs), y0 = (int)floorf(ys);
    float tx = xs - (float)x0, ty = ys - (float)y0;
    float wx[4], wy[4]; int ix[4], iy[4];
    #pragma unroll
    for (int k = 0; k < 4; k++) {
        wx[k] = cubicw(tx - (float)(k-1)); ix[k] = min(max(x0 + k - 1, 0), 17);
        wy[k] = cubicw(ty - (float)(k-1)); iy[k] = min(max(y0 + k - 1, 0), 17);
    }
    const float* f = g_f0 + bc*324;
    float acc = 0.f;
    #pragma unroll
    for (int i = 0; i < 4; i++) {
        float r = 0.f;
        #pragma unroll
        for (int j = 0; j < 4; j++) r += wx[j] * f[iy[i]*18 + ix[j]];
        acc += wy[i] * r;
    }
    g_bufA[idx] = acc;
}

// --------------------------------------------------------------- q-proj ----
// 2 pixels per thread, all 4 stages; weight LDS amortized 2x; pixel-major
// uint4 stores (as in the proven Round-5 layout). Block = 256 threads covers
// 512 consecutive pixels; PLANE = 98*512 exactly, so no block straddles images.
__global__ __launch_bounds__(256)
void qproj_kernel(const float* __restrict__ guidance,
                  const float* __restrict__ w1s, const float* __restrict__ b1s,
                  const float* __restrict__ w2s, const float* __restrict__ b2s)
{
    __shared__ float   s_w1[4*96];
    __shared__ float   s_b1[4*32];
    __shared__ float   s_b2[4*32];
    __shared__ __half2 s_w2[4*32*16];   // [stage][out j][in pair k]

    const int tid = threadIdx.x;
    for (int i = tid; i < 4*96; i += 256) s_w1[i] = w1s[i];
    for (int i = tid; i < 4*32; i += 256) { s_b1[i] = b1s[i]; s_b2[i] = b2s[i]; }
    for (int i = tid; i < 4*32*16; i += 256) {
        int k = i & 15; int sj = i >> 4;
        s_w2[i] = __floats2half2_rn(w2s[sj*32 + 2*k], w2s[sj*32 + 2*k + 1]);
    }
    __syncthreads();

    const int P0 = blockIdx.x * 512 + tid;    // global pixel, second pixel at +256
    const int b  = blockIdx.x / 98;
    const int gi0 = P0 - b * PLANE;
    const float* gb = guidance + (size_t)b * 3 * PLANE;

    float g0[2], g1[2], g2[2];
    #pragma unroll
    for (int i = 0; i < 2; i++) {
        int gi = gi0 + i*256;
        g0[i] = gb[gi]; g1[i] = gb[PLANE + gi]; g2[i] = gb[2*PLANE + gi];
    }

    #pragma unroll 1
    for (int s = 0; s < 4; s++) {
        const float* w1 = s_w1 + s*96;
        const float* b1 = s_b1 + s*32;
        const float* b2 = s_b2 + s*32;
        const __half2* w2 = s_w2 + s*32*16;

        __half2 h2[2][16];
        #pragma unroll
        for (int k = 0; k < 16; k++) {
            float wa0 = w1[(2*k)*3], wa1 = w1[(2*k)*3+1], wa2 = w1[(2*k)*3+2], ba = b1[2*k];
            float wb0 = w1[(2*k+1)*3], wb1 = w1[(2*k+1)*3+1], wb2 = w1[(2*k+1)*3+2], bb = b1[2*k+1];
            #pragma unroll
            for (int i = 0; i < 2; i++) {
                float va = fmaf(wa0, g0[i], fmaf(wa1, g1[i], fmaf(wa2, g2[i], ba)));
                float vb = fmaf(wb0, g0[i], fmaf(wb1, g1[i], fmaf(wb2, g2[i], bb)));
                h2[i][k] = __floats2half2_rn(gelu_fast(va), gelu_fast(vb));
            }
        }

        // out[i][jj] packs channels (2jj, 2jj+1) of pixel i
        unsigned int outp[2][16];
        #pragma unroll
        for (int jj = 0; jj < 16; jj++) {
            const __half2* wr0 = w2 + (2*jj)*16;
            const __half2* wr1 = wr0 + 16;
            __half2 a0[2], a1[2];
            #pragma unroll
            for (int i = 0; i < 2; i++) { a0[i] = __float2half2_rn(0.f); a1[i] = a0[i]; }
            #pragma unroll
            for (int k = 0; k < 16; k++) {
                __half2 w0 = wr0[k], w1h = wr1[k];
                #pragma unroll
                for (int i = 0; i < 2; i++) {
                    a0[i] = __hfma2(h2[i][k], w0,  a0[i]);
                    a1[i] = __hfma2(h2[i][k], w1h, a1[i]);
                }
            }
            float c0 = b2[2*jj], c1 = b2[2*jj+1];
            #pragma unroll
            for (int i = 0; i < 2; i++) {
                float2 f0 = __half22float2(a0[i]);
                float2 f1 = __half22float2(a1[i]);
                __half2 qv = __floats2half2_rn(f0.x + f0.y + c0, f1.x + f1.y + c1);
                outp[i][jj] = *reinterpret_cast<unsigned int*>(&qv);
            }
        }
        #pragma unroll
        for (int i = 0; i < 2; i++) {
            uint4* dst = (uint4*)(g_q + ((size_t)s*8*PLANE + P0 + i*256) * CH);
            const uint4* src = (const uint4*)outp[i];
            dst[0] = src[0]; dst[1] = src[1]; dst[2] = src[2]; dst[3] = src[3];
        }
    }
}

// ------------------------------------------------------------- fused JBU ----
// Identical to the proven Round-5 kernel (64.2 us/launch).
__global__ __launch_bounds__(256, 2)
void jbu_kernel(const float* __restrict__ temp_p, const float* __restrict__ sigma_p,
                int stage, int src_sel, int dst_sel, float* __restrict__ dst_ext)
{
    const float* hr_in = (src_sel == 0) ? g_bufA : g_bufB;
    float* out = (dst_sel == 2) ? dst_ext : ((dst_sel == 0) ? g_bufA : g_bufB);

    extern __shared__ float smem[];
    float* shr = smem;                      // [3][NPIX] = 1452
    float* ssp = shr + 3*NPIX;              // 49 -> 1501
    __half* sq = (__half*)(smem + 1504);    // 16B aligned

    const int tid = threadIdx.x;
    const int b   = blockIdx.z;
    const int ty0 = blockIdx.y * TS, tx0 = blockIdx.x * TS;

    if (tid < NP) {
        float sig = *sigma_p;
        int di = tid / 7, dj = tid % 7;
        float dy = -1.0f + (float)di * (1.0f/3.0f);
        float dx = -1.0f + (float)dj * (1.0f/3.0f);
        ssp[tid] = expf(-(dy*dy + dx*dx) / (2.0f*sig*sig));
    }

    const float*  hb = hr_in + (size_t)b * 3 * PLANE;
    const __half* qg = g_q + ((size_t)stage*8 + b) * PLANE * CH;

    // Halo fill: hr (fp32) + precomputed q (fp16, straight copy gmem->smem).
    for (int i = tid; i < NPIX; i += 256) {
        int ly = i / THALO, lx = i % THALO;
        int gy = refl(ty0 + ly - HALO, GHH);
        int gx = refl(tx0 + lx - HALO, GWW);
        int gi = gy * GWW + gx;
        shr[i]        = hb[gi];
        shr[NPIX+i]   = hb[PLANE + gi];
        shr[2*NPIX+i] = hb[2*PLANE + gi];
        const uint4* qs = (const uint4*)(qg + (size_t)gi * CH);
        uint4* qd = (uint4*)(sq + i * CHP_H);
        qd[0] = qs[0]; qd[1] = qs[1]; qd[2] = qs[2]; qd[3] = qs[3];
    }
    __syncthreads();

    const int ty = tid / TS, tx = tid % TS;
    const int base = ty * THALO + tx;                  // top-left (di=0,dj=0) tap
    const __half* qb = sq + base * CHP_H;
    const __half* qc = sq + (base + HALO*THALO + HALO) * CHP_H;

    __half2 s2[NP];
    #pragma unroll
    for (int p = 0; p < NP; p++) s2[p] = __float2half2_rn(0.f);

    #pragma unroll 1
    for (int c4 = 0; c4 < 4; c4++) {           // 8 channels per iteration
        uint4 cu = ((const uint4*)qc)[c4];
        __half2 c0 = h2cast(cu.x), c1 = h2cast(cu.y), c2 = h2cast(cu.z), c3 = h2cast(cu.w);
        #pragma unroll
        for (int p = 0; p < NP; p++) {
            const int di = p / 7, dj = p % 7;
            uint4 tu = ((const uint4*)(qb + (di*THALO + dj)*CHP_H))[c4];
            __half2 acc = s2[p];
            acc = __hfma2(c0, h2cast(tu.x), acc);
            acc = __hfma2(c1, h2cast(tu.y), acc);
            acc = __hfma2(c2, h2cast(tu.z), acc);
            acc = __hfma2(c3, h2cast(tu.w), acc);
            s2[p] = acc;
        }
    }

    float tmp = expf(*temp_p);
    tmp = fminf(fmaxf(tmp, 1e-4f), 1e4f);

    float s[NP];
    float m = -1e30f;
    #pragma unroll
    for (int p = 0; p < NP; p++) {
        float2 f = __half22float2(s2[p]);
        s[p] = (f.x + f.y) * tmp;
        m = fmaxf(m, s[p]);
    }
    float sum = 0.f;
    #pragma unroll
    for (int p = 0; p < NP; p++) {
        float e = __expf(s[p] - m) * ssp[p];
        s[p] = e; sum += e;
    }
    float inv = 1.0f / fmaxf(sum, 1e-7f);

    float o0 = 0.f, o1 = 0.f, o2 = 0.f;
    #pragma unroll
    for (int p = 0; p < NP; p++) {
        const int di = p / 7, dj = p % 7;
        int ti = base + di*THALO + dj;
        o0 += s[p] * shr[ti];
        o1 += s[p] * shr[NPIX + ti];
        o2 += s[p] * shr[2*NPIX + ti];
    }
    int y = ty0 + ty, x = tx0 + tx;
    size_t ob = (size_t)b * 3 * PLANE + (size_t)y * GWW + x;
    out[ob]           = o0 * inv;
    out[ob +   PLANE] = o1 * inv;
    out[ob + 2*PLANE] = o2 * inv;
}

// ----------------------------------------------------------------- launch ----
extern "C" void kernel_launch(void* const* d_in, const int* in_sizes, int n_in,
                              void* d_out, int out_size)
{
    const float* x      = (const float*)d_in[0];
    const float* gd     = (const float*)d_in[1];
    const float* lw     = (const float*)d_in[2];
    const float* lb     = (const float*)d_in[3];
    const float* w1s    = (const float*)d_in[4];
    const float* b1s    = (const float*)d_in[5];
    const float* w2s    = (const float*)d_in[6];
    const float* b2s    = (const float*)d_in[7];
    const float* temps  = (const float*)d_in[8];
    const float* sigmas = (const float*)d_in[9];
    float* out = (float*)d_out;

    const int smem = 1504*4 + NPIX * CHP_H * 2;   // 6016 + 38720 = 44736 B
    static int smem_set = 0;
    if (!smem_set) {
        cudaFuncSetAttribute(jbu_kernel, cudaFuncAttributeMaxDynamicSharedMemorySize, smem);
        smem_set = 1;
    }

    linear_kernel<<<(8*972 + 3)/4, 128>>>(x, lw, lb);
    bicubic18_kernel<<<(8*3*PLANE + 255)/256, 256>>>();
    qproj_kernel<<<8*PLANE/512, 256>>>(gd, w1s, b1s, w2s, b2s);

    dim3 grid(GWW/TS, GHH/TS, 8);
    jbu_kernel<<<grid, 256, smem>>>(temps + 0, sigmas + 0, 0, 0, 1, nullptr);
    jbu_kernel<<<grid, 256, smem>>>(temps + 1, sigmas + 1, 1, 1, 0, nullptr);
    jbu_kernel<<<grid, 256, smem>>>(temps + 2, sigmas + 2, 2, 0, 1, nullptr);
    jbu_kernel<<<grid, 256, smem>>>(temps + 3, sigmas + 3, 3, 1, 2, out);
}